// round 15
// baseline (speedup 1.0000x reference)
#include <cuda_runtime.h>
#include <math.h>
#include <stdint.h>

#define B_   2
#define S_   2048
#define D_   1024
#define H_   16
#define HD_  64
#define KJL  32
#define M_   (B_*S_)
#define NF   2048         // folded qkv width: 512 qjl | 512 kjl | 1024 v

// ---- scratch (device globals: allocation is forbidden) --------------------
__device__ float g_wf[NF*D_];     // folded weights, TRANSPOSED [n][k], tf32
__device__ float g_bf[NF];        // folded bias (fp32)
__device__ float g_x2[M_*NF];     // folded qkv output (tf32-rounded by epilogue)
__device__ float g_ao[M_*D_];     // attention output (tf32-rounded)
__device__ float g_xr[M_*D_];     // tf32-rounded input X
__device__ float g_wpt[D_*D_];    // W_proj TRANSPOSED [n][k], tf32

__device__ __forceinline__ float rtf32(float x) {
    asm("cvt.rna.tf32.f32 %0, %1;" : "=f"(x) : "f"(x));
    return x;
}
__device__ __forceinline__ void cpa16(uint32_t dst, const void* src) {
    asm volatile("cp.async.cg.shared.global [%0], [%1], 16;" :: "r"(dst), "l"(src));
}
__device__ __forceinline__ void cp_commit() {
    asm volatile("cp.async.commit_group;");
}
template<int N> __device__ __forceinline__ void cp_wait() {
    asm volatile("cp.async.wait_group %0;" :: "n"(N));
}
__device__ __forceinline__ void ldsm4(uint32_t& r0, uint32_t& r1,
                                      uint32_t& r2, uint32_t& r3, uint32_t addr) {
    asm volatile("ldmatrix.sync.aligned.m8n8.x4.shared.b16 {%0,%1,%2,%3}, [%4];"
                 : "=r"(r0), "=r"(r1), "=r"(r2), "=r"(r3) : "r"(addr));
}
__device__ __forceinline__ void mma8(float4& d, const uint32_t* a,
                                     uint32_t b0, uint32_t b1)
{
    asm volatile(
        "mma.sync.aligned.m16n8k8.row.col.f32.tf32.tf32.f32 "
        "{%0,%1,%2,%3},{%4,%5,%6,%7},{%8,%9},{%0,%1,%2,%3};"
        : "+f"(d.x), "+f"(d.y), "+f"(d.z), "+f"(d.w)
        : "r"(a[0]), "r"(a[1]), "r"(a[2]), "r"(a[3]), "r"(b0), "r"(b1));
}

// ===========================================================================
// Merged prep (unchanged from round 14)
// ===========================================================================
#define NB_SPLIT 16384
#define NB_TR    2048
#define NB_FOLD  256
#define NB_BIAS  8
#define NB_ALL   (NB_SPLIT + NB_TR + NB_FOLD + NB_BIAS)

__global__ __launch_bounds__(256)
void prep_all(const float* __restrict__ X,   const float* __restrict__ Wat,
              const float* __restrict__ bat, const float* __restrict__ Sp,
              const float* __restrict__ Wp,
              float* __restrict__ xr,  float* __restrict__ wpt,
              float* __restrict__ wf,  float* __restrict__ bf)
{
    __shared__ float sbuf[128*65 + 32*64];
    const int bid = blockIdx.x;
    const int tid = threadIdx.x;

    if (bid < NB_SPLIT) {
        int i = bid * 256 + tid;
        xr[i] = rtf32(X[i]);

    } else if (bid < NB_SPLIT + NB_TR) {
        float (*sm)[33] = (float(*)[33])sbuf;
        const int rem = bid - NB_SPLIT;
        const int z  = rem >> 10;
        const int bx = (rem & 31) * 32;
        const int by = ((rem >> 5) & 31) * 32;
        const float* src; float* dst; int lds, off;
        if (z == 0) { src = Wp;  dst = wpt;           lds = 1024; off = 0;    }
        else        { src = Wat; dst = wf + 1024*D_;  lds = 3072; off = 2048; }
        const int tx = tid & 31, ty = tid >> 5;
        #pragma unroll
        for (int j = 0; j < 4; j++) {
            int r = ty*4 + j;
            sm[r][tx] = src[(long)(by + r)*lds + off + bx + tx];
        }
        __syncthreads();
        #pragma unroll
        for (int j = 0; j < 4; j++) {
            int r = ty*4 + j;
            dst[(long)(bx + r)*D_ + by + tx] = rtf32(sm[tx][r]);
        }

    } else if (bid < NB_SPLIT + NB_TR + NB_FOLD) {
        float (*slab)[65] = (float(*)[65])sbuf;
        float (*sp)[64]   = (float(*)[64])(sbuf + 128*65);
        const int rem  = bid - NB_SPLIT - NB_TR;
        const int d0   = (rem & 7) * 128;
        const int ph   = rem >> 3;
        const int part = ph >> 4, h = ph & 15;
        const int base = part*1024 + h*64;

        #pragma unroll
        for (int it = 0; it < 32; it++) {
            int i = tid + it*256;
            slab[i >> 6][i & 63] = Wat[(long)(d0 + (i >> 6))*(3*D_) + base + (i & 63)];
        }
        #pragma unroll
        for (int it = 0; it < 8; it++) {
            int i = tid + it*256;
            sp[i >> 6][i & 63] = Sp[i];
        }
        __syncthreads();

        const int dl = tid & 127;
        const int k0 = (tid >> 7) * 16;
        for (int k = k0; k < k0 + 16; k++) {
            float a = 0.f;
            #pragma unroll
            for (int e = 0; e < 64; e++) a += slab[dl][e] * sp[k][e];
            wf[(long)(part*512 + h*32 + k)*D_ + d0 + dl] = rtf32(a);
        }

    } else {
        const int i = (bid - NB_SPLIT - NB_TR - NB_FOLD) * 256 + tid;
        if (i < NF) {
            if (i < 1024) {
                const int part = i >> 9, hk = i & 511, h = hk >> 5, k = hk & 31;
                float a = 0.f;
                #pragma unroll
                for (int e = 0; e < HD_; e++)
                    a += bat[part*1024 + h*HD_ + e] * Sp[k*HD_ + e];
                bf[i] = a;
            } else {
                bf[i] = bat[2048 + (i - 1024)];
            }
        }
    }
}

// ===========================================================================
// TF32 GEMM (TN) — unchanged from round 14 (proven: 55.6us, tensor=51%).
// ===========================================================================
#define GBM 128
#define GBN 128
#define GBK 16
#define LDT 20
#define STG 3
#define TSTAGE (128*LDT*4)

__global__ __launch_bounds__(128, 2)
void tf32_gemm_tn(const float* __restrict__ A, const float* __restrict__ BT,
                  const float* __restrict__ bias, float* __restrict__ C,
                  int M, int N, int K, int roundC)
{
    extern __shared__ float dyn[];
    float* As = dyn;
    float* Bs = dyn + STG*128*LDT;

    const int tid  = threadIdx.x;
    const int wid  = tid >> 5;
    const int lane = tid & 31;
    const int g    = lane >> 2;
    const int t    = lane & 3;
    const int brow = blockIdx.y * GBM;
    const int bcol = blockIdx.x * GBN;
    const int wm   = (wid & 1) * 64;
    const int wn   = (wid >> 1) * 64;

    float4 acc[4][8];
    #pragma unroll
    for (int nt = 0; nt < 8; nt++) {
        float2 bb = *(const float2*)&bias[bcol + wn + nt*8 + 2*t];
        #pragma unroll
        for (int i = 0; i < 4; i++)
            acc[i][nt] = make_float4(bb.x, bb.y, bb.x, bb.y);
    }

    const int lr = tid >> 2;
    const int lc = (tid & 3) << 2;
    const float* Ag = A  + (long)(brow + lr)*K + lc;
    const float* Bg = BT + (long)(bcol + lr)*K + lc;
    const uint32_t sA = (uint32_t)__cvta_generic_to_shared(As);
    const uint32_t sB = (uint32_t)__cvta_generic_to_shared(Bs);
    const uint32_t ldoff = (lr*LDT + lc) * 4;

    const uint32_t a_off = (((wm + (lane & 15))*LDT) + ((lane >> 4) << 2)) * 4;
    const uint32_t b_off = (((wn + (lane & 7 ))*LDT) + ((lane >> 3) << 2)) * 4;

    const int KC = K / GBK;
    int fetch = 0;

    #pragma unroll
    for (int p = 0; p < STG - 1; p++) {
        #pragma unroll
        for (int i = 0; i < 4; i++) {
            cpa16(sA + p*TSTAGE + ldoff + i*(32*LDT*4), Ag + (long)i*32*K + fetch*GBK);
            cpa16(sB + p*TSTAGE + ldoff + i*(32*LDT*4), Bg + (long)i*32*K + fetch*GBK);
        }
        cp_commit();
        fetch++;
    }

    int s = 0;
    for (int c = 0; c < KC; c++) {
        cp_wait<STG - 2>();
        __syncthreads();

        const uint32_t aS = sA + s*TSTAGE;
        const uint32_t bS = sB + s*TSTAGE;

        uint32_t bfr[8][4];
        #pragma unroll
        for (int nt = 0; nt < 8; nt++)
            ldsm4(bfr[nt][0], bfr[nt][1], bfr[nt][2], bfr[nt][3],
                  bS + b_off + nt*(8*LDT*4));

        #pragma unroll
        for (int kk2 = 0; kk2 < 2; kk2++) {
            uint32_t af[4][4];
            #pragma unroll
            for (int i = 0; i < 4; i++)
                ldsm4(af[i][0], af[i][1], af[i][2], af[i][3],
                      aS + a_off + (i*16*LDT + kk2*8)*4);
            #pragma unroll
            for (int i = 0; i < 4; i++)
                #pragma unroll
                for (int nt = 0; nt < 8; nt++)
                    mma8(acc[i][nt], af[i], bfr[nt][kk2*2], bfr[nt][kk2*2 + 1]);
        }

        if (fetch < KC) {
            const int p = (s + STG - 1) >= STG ? s - 1 : s + STG - 1;
            #pragma unroll
            for (int i = 0; i < 4; i++) {
                cpa16(sA + p*TSTAGE + ldoff + i*(32*LDT*4), Ag + (long)i*32*K + fetch*GBK);
                cpa16(sB + p*TSTAGE + ldoff + i*(32*LDT*4), Bg + (long)i*32*K + fetch*GBK);
            }
            fetch++;
        }
        cp_commit();
        s = (s + 1 == STG) ? 0 : s + 1;
    }

    #pragma unroll
    for (int i = 0; i < 4; i++) {
        const long r0 = brow + wm + i*16 + g;
        #pragma unroll
        for (int nt = 0; nt < 8; nt++) {
            const int c0 = bcol + wn + nt*8 + 2*t;
            float4 v = acc[i][nt];
            if (roundC) {
                v.x = rtf32(v.x); v.y = rtf32(v.y);
                v.z = rtf32(v.z); v.w = rtf32(v.w);
            }
            *(float2*)&C[r0*N + c0]       = make_float2(v.x, v.y);
            *(float2*)&C[(r0 + 8)*N + c0] = make_float2(v.z, v.w);
        }
    }
}

// ===========================================================================
// Tensor-core causal flash attention (m16n8k8 tf32).
// NEW: 128 queries/block (4 warps x 2 sequential 16-row subtiles) — halves
// K/V smem traffic + syncs per query; ldmatrix for K fragments (64 scalar
// LDS -> 16 LDSM per subtile; mapping identical to the proven GEMM path).
// grid = (S/128, H, B), heavy q-tiles first, 3 blocks/SM.
// ===========================================================================
#define LDK 36
#define LDV 68
#define KBYTES (64*LDK*4)
#define VBYTES (64*LDV*4)

__global__ __launch_bounds__(128, 3)
void attn_mma(const float* __restrict__ x2, float* __restrict__ ao)
{
    extern __shared__ float smem[];
    float* Ks = smem;                 // [2][64*LDK]
    float* Vs = smem + 2*64*LDK;      // [2][64*LDV]

    const int tid  = threadIdx.x;
    const int w    = tid >> 5;
    const int lane = tid & 31;
    const int g    = lane >> 2;
    const int t    = lane & 3;
    const int h    = blockIdx.y;
    const int b    = blockIdx.z;
    const int qtb  = gridDim.x - 1 - blockIdx.x;   // heavy tiles first
    const int q0   = qtb * 128;

    const uint32_t sK = (uint32_t)__cvta_generic_to_shared(Ks);
    const uint32_t sV = (uint32_t)__cvta_generic_to_shared(Vs);

    const int kr = tid >> 3, kc = (tid & 7) << 2;
    const int vr = tid >> 4, vc = (tid & 15) << 2;
    const float* kbase = x2 + (long)(b*S_) * NF + 512  + h*KJL;
    const float* vbase = x2 + (long)(b*S_) * NF + 1024 + h*HD_;

    #define LOAD_TILE(kt_, bb_)                                                 \
    {                                                                           \
        const float* kb = kbase + (long)((kt_)*64 + kr) * NF + kc;              \
        const float* vb = vbase + (long)((kt_)*64 + vr) * NF + vc;              \
        uint32_t dk = sK + (bb_)*KBYTES + (kr*LDK + kc)*4;                      \
        uint32_t dv = sV + (bb_)*VBYTES + (vr*LDV + vc)*4;                      \
        _Pragma("unroll")                                                       \
        for (int i_ = 0; i_ < 4; i_++)                                          \
            cpa16(dk + i_*(16*LDK*4), kb + (long)i_*16*NF);                     \
        _Pragma("unroll")                                                       \
        for (int i_ = 0; i_ < 8; i_++)                                          \
            cpa16(dv + i_*(8*LDV*4),  vb + (long)i_*8*NF);                      \
    }

    // ---- Q fragments for both subtiles (straight from gmem, tf32) ---------
    uint32_t qf[2][4][4];
    #pragma unroll
    for (int sdx = 0; sdx < 2; sdx++) {
        const float* qb = x2 + (long)(b*S_ + q0 + sdx*64) * NF + h*KJL;
        #pragma unroll
        for (int ks = 0; ks < 4; ks++) {
            qf[sdx][ks][0] = __float_as_uint(qb[(long)(w*16 + g    )*NF + ks*8 + t    ]);
            qf[sdx][ks][1] = __float_as_uint(qb[(long)(w*16 + g + 8)*NF + ks*8 + t    ]);
            qf[sdx][ks][2] = __float_as_uint(qb[(long)(w*16 + g    )*NF + ks*8 + t + 4]);
            qf[sdx][ks][3] = __float_as_uint(qb[(long)(w*16 + g + 8)*NF + ks*8 + t + 4]);
        }
    }

    float4 oacc[2][8];
    #pragma unroll
    for (int sdx = 0; sdx < 2; sdx++)
        #pragma unroll
        for (int nt = 0; nt < 8; nt++) oacc[sdx][nt] = make_float4(0.f, 0.f, 0.f, 0.f);
    float m0[2] = {-1e30f, -1e30f}, m1[2] = {-1e30f, -1e30f};
    float l0[2] = {0.f, 0.f},       l1[2] = {0.f, 0.f};

    const int nkt = 2*qtb + 2;
    const int lq0 = (lane & ~3) | (t >> 1);
    const int lq1 = lq0 + 2;
    // ldmatrix per-thread offset within K tile (same pattern as GEMM B)
    const uint32_t kf_off = (((lane & 7)*LDK) + ((lane >> 3) << 2)) * 4;

    LOAD_TILE(0, 0);
    cp_commit();

    int buf = 0;
    for (int kt = 0; kt < nkt; kt++) {
        if (kt + 1 < nkt) {
            LOAD_TILE(kt + 1, buf ^ 1);
            cp_commit();
            cp_wait<1>();
        } else {
            cp_wait<0>();
        }
        __syncthreads();

        const uint32_t sKb = sK + buf * KBYTES;
        const float* Vb = Vs + buf * (64*LDV);

        #pragma unroll
        for (int sdx = 0; sdx < 2; sdx++) {
            const int R0 = q0 + sdx*64 + w*16 + g;
            const int R1 = R0 + 8;
            if (kt*64 > q0 + sdx*64 + w*16 + 15) continue;   // fully masked

            // ---- S = Q @ K^T (ldmatrix-fed B fragments) --------------------
            float4 sa[8];
            #pragma unroll
            for (int nt = 0; nt < 8; nt++) {
                uint32_t k0[4], k1[4];
                const uint32_t a0 = sKb + kf_off + nt*(8*LDK*4);
                ldsm4(k0[0], k0[1], k0[2], k0[3], a0);        // k 0..15
                ldsm4(k1[0], k1[1], k1[2], k1[3], a0 + 64);   // k 16..31
                sa[nt] = make_float4(0.f, 0.f, 0.f, 0.f);
                mma8(sa[nt], qf[sdx][0], k0[0], k0[1]);
                mma8(sa[nt], qf[sdx][1], k0[2], k0[3]);
                mma8(sa[nt], qf[sdx][2], k1[0], k1[1]);
                mma8(sa[nt], qf[sdx][3], k1[2], k1[3]);
            }

            // ---- scale + causal mask + online softmax ----------------------
            float mx0 = -1e30f, mx1 = -1e30f;
            #pragma unroll
            for (int nt = 0; nt < 8; nt++) {
                const int c0 = kt*64 + nt*8 + 2*t;
                const int c1 = c0 + 1;
                sa[nt].x = (c0 <= R0) ? sa[nt].x * 0.125f : -1e30f;
                sa[nt].y = (c1 <= R0) ? sa[nt].y * 0.125f : -1e30f;
                sa[nt].z = (c0 <= R1) ? sa[nt].z * 0.125f : -1e30f;
                sa[nt].w = (c1 <= R1) ? sa[nt].w * 0.125f : -1e30f;
                mx0 = fmaxf(mx0, fmaxf(sa[nt].x, sa[nt].y));
                mx1 = fmaxf(mx1, fmaxf(sa[nt].z, sa[nt].w));
            }
            mx0 = fmaxf(mx0, __shfl_xor_sync(0xffffffff, mx0, 1));
            mx0 = fmaxf(mx0, __shfl_xor_sync(0xffffffff, mx0, 2));
            mx1 = fmaxf(mx1, __shfl_xor_sync(0xffffffff, mx1, 1));
            mx1 = fmaxf(mx1, __shfl_xor_sync(0xffffffff, mx1, 2));

            const float nm0 = fmaxf(m0[sdx], mx0);
            const float nm1 = fmaxf(m1[sdx], mx1);
            const float sc0 = __expf(m0[sdx] - nm0);
            const float sc1 = __expf(m1[sdx] - nm1);

            float ps0 = 0.f, ps1 = 0.f;
            #pragma unroll
            for (int nt = 0; nt < 8; nt++) {
                sa[nt].x = __expf(sa[nt].x - nm0);
                sa[nt].y = __expf(sa[nt].y - nm0);
                sa[nt].z = __expf(sa[nt].z - nm1);
                sa[nt].w = __expf(sa[nt].w - nm1);
                ps0 += sa[nt].x + sa[nt].y;
                ps1 += sa[nt].z + sa[nt].w;
            }
            ps0 += __shfl_xor_sync(0xffffffff, ps0, 1);
            ps0 += __shfl_xor_sync(0xffffffff, ps0, 2);
            ps1 += __shfl_xor_sync(0xffffffff, ps1, 1);
            ps1 += __shfl_xor_sync(0xffffffff, ps1, 2);

            l0[sdx] = l0[sdx] * sc0 + ps0;  m0[sdx] = nm0;
            l1[sdx] = l1[sdx] * sc1 + ps1;  m1[sdx] = nm1;

            #pragma unroll
            for (int nt = 0; nt < 8; nt++) {
                oacc[sdx][nt].x *= sc0;  oacc[sdx][nt].y *= sc0;
                oacc[sdx][nt].z *= sc1;  oacc[sdx][nt].w *= sc1;
            }

            // ---- O += P @ V (shuffle-based P reshape) ----------------------
            #pragma unroll
            for (int ks = 0; ks < 8; ks++) {
                float x0 = __shfl_sync(0xffffffff, sa[ks].x, lq0);
                float y0 = __shfl_sync(0xffffffff, sa[ks].y, lq0);
                float z0 = __shfl_sync(0xffffffff, sa[ks].z, lq0);
                float w0 = __shfl_sync(0xffffffff, sa[ks].w, lq0);
                float x1 = __shfl_sync(0xffffffff, sa[ks].x, lq1);
                float y1 = __shfl_sync(0xffffffff, sa[ks].y, lq1);
                float z1 = __shfl_sync(0xffffffff, sa[ks].z, lq1);
                float w1 = __shfl_sync(0xffffffff, sa[ks].w, lq1);
                uint32_t pa[4];
                pa[0] = __float_as_uint(rtf32((t & 1) ? y0 : x0));
                pa[1] = __float_as_uint(rtf32((t & 1) ? w0 : z0));
                pa[2] = __float_as_uint(rtf32((t & 1) ? y1 : x1));
                pa[3] = __float_as_uint(rtf32((t & 1) ? w1 : z1));

                const int kr0 = (ks*8 + t    ) * LDV + g;
                const int kr1 = (ks*8 + t + 4) * LDV + g;
                #pragma unroll
                for (int nt = 0; nt < 8; nt++) {
                    uint32_t b0 = __float_as_uint(Vb[kr0 + nt*8]);
                    uint32_t b1 = __float_as_uint(Vb[kr1 + nt*8]);
                    mma8(oacc[sdx][nt], pa, b0, b1);
                }
            }
        }
        __syncthreads();
        buf ^= 1;
    }

    // ---- normalize + store (tf32-rounded for the following GEMM) ----------
    #pragma unroll
    for (int sdx = 0; sdx < 2; sdx++) {
        const int R0 = q0 + sdx*64 + w*16 + g;
        const float inv0 = 1.f / l0[sdx];
        const float inv1 = 1.f / l1[sdx];
        float* o0 = ao + (long)(b*S_ + R0) * D_ + h*HD_;
        float* o1 = ao + (long)(b*S_ + R0 + 8) * D_ + h*HD_;
        #pragma unroll
        for (int nt = 0; nt < 8; nt++) {
            *(float2*)(o0 + nt*8 + 2*t) =
                make_float2(rtf32(oacc[sdx][nt].x * inv0), rtf32(oacc[sdx][nt].y * inv0));
            *(float2*)(o1 + nt*8 + 2*t) =
                make_float2(rtf32(oacc[sdx][nt].z * inv1), rtf32(oacc[sdx][nt].w * inv1));
        }
    }
}

// ===========================================================================
extern "C" void kernel_launch(void* const* d_in, const int* in_sizes, int n_in,
                              void* d_out, int out_size)
{
    const float* X    = (const float*)d_in[0];
    const float* Wat  = (const float*)d_in[1];
    const float* bat  = (const float*)d_in[2];
    const float* Sp   = (const float*)d_in[3];
    const float* Wp   = (const float*)d_in[4];
    const float* bp   = (const float*)d_in[5];
    float* out = (float*)d_out;

    float *wf, *bf, *x2, *ao, *xr, *wpt;
    cudaGetSymbolAddress((void**)&wf,  g_wf);
    cudaGetSymbolAddress((void**)&bf,  g_bf);
    cudaGetSymbolAddress((void**)&x2,  g_x2);
    cudaGetSymbolAddress((void**)&ao,  g_ao);
    cudaGetSymbolAddress((void**)&xr,  g_xr);
    cudaGetSymbolAddress((void**)&wpt, g_wpt);

    const int gemmSmem = 2 * STG * 128 * LDT * 4;             // 61440 B
    const int attnSmem = 2 * (64*LDK + 64*LDV) * 4;           // 53248 B
    cudaFuncSetAttribute(tf32_gemm_tn,
                         cudaFuncAttributeMaxDynamicSharedMemorySize, gemmSmem);
    cudaFuncSetAttribute(attn_mma,
                         cudaFuncAttributeMaxDynamicSharedMemorySize, attnSmem);

    // 0. ALL prep in one launch
    prep_all<<<NB_ALL, 256>>>(X, Wat, bat, Sp, Wp, xr, wpt, wf, bf);

    // 1. folded QKV GEMM (epilogue rounds x2 to tf32)
    dim3 g1(NF/GBN, M_/GBM);
    tf32_gemm_tn<<<g1, 128, gemmSmem>>>(xr, wf, bf, x2, M_, NF, D_, 1);

    // 2. causal flash attention (128 queries/block)
    dim3 g3(S_/128, H_, B_);
    attn_mma<<<g3, 128, attnSmem>>>(x2, ao);

    // 3. output projection GEMM (raw fp32 output)
    dim3 g4(D_/GBN, M_/GBM);
    tf32_gemm_tn<<<g4, 128, gemmSmem>>>(ao, wpt, bp, out, M_, D_, D_, 0);
}

// round 17
// speedup vs baseline: 1.0770x; 1.0770x over previous
#include <cuda_runtime.h>
#include <math.h>
#include <stdint.h>

#define B_   2
#define S_   2048
#define D_   1024
#define H_   16
#define HD_  64
#define KJL  32
#define M_   (B_*S_)
#define NF   2048         // folded qkv width: 512 qjl | 512 kjl | 1024 v

// ---- scratch (device globals: allocation is forbidden) --------------------
__device__ float g_wf[NF*D_];     // folded weights, TRANSPOSED [n][k], tf32
__device__ float g_bf[NF];        // folded bias (fp32)
__device__ float g_x2[M_*NF];     // folded qkv output (tf32-rounded by epilogue)
__device__ float g_ao[M_*D_];     // attention output (tf32-rounded)
__device__ float g_xr[M_*D_];     // tf32-rounded input X
__device__ float g_wpt[D_*D_];    // W_proj TRANSPOSED [n][k], tf32

__device__ __forceinline__ float rtf32(float x) {
    asm("cvt.rna.tf32.f32 %0, %1;" : "=f"(x) : "f"(x));
    return x;
}
__device__ __forceinline__ void cpa16(uint32_t dst, const void* src) {
    asm volatile("cp.async.cg.shared.global [%0], [%1], 16;" :: "r"(dst), "l"(src));
}
__device__ __forceinline__ void cp_commit() {
    asm volatile("cp.async.commit_group;");
}
template<int N> __device__ __forceinline__ void cp_wait() {
    asm volatile("cp.async.wait_group %0;" :: "n"(N));
}
__device__ __forceinline__ void ldsm4(uint32_t& r0, uint32_t& r1,
                                      uint32_t& r2, uint32_t& r3, uint32_t addr) {
    asm volatile("ldmatrix.sync.aligned.m8n8.x4.shared.b16 {%0,%1,%2,%3}, [%4];"
                 : "=r"(r0), "=r"(r1), "=r"(r2), "=r"(r3) : "r"(addr));
}
__device__ __forceinline__ void mma8(float4& d, const uint32_t* a,
                                     uint32_t b0, uint32_t b1)
{
    asm volatile(
        "mma.sync.aligned.m16n8k8.row.col.f32.tf32.tf32.f32 "
        "{%0,%1,%2,%3},{%4,%5,%6,%7},{%8,%9},{%0,%1,%2,%3};"
        : "+f"(d.x), "+f"(d.y), "+f"(d.z), "+f"(d.w)
        : "r"(a[0]), "r"(a[1]), "r"(a[2]), "r"(a[3]), "r"(b0), "r"(b1));
}

// ===========================================================================
// Merged prep (unchanged from round 14)
// ===========================================================================
#define NB_SPLIT 16384
#define NB_TR    2048
#define NB_FOLD  256
#define NB_BIAS  8
#define NB_ALL   (NB_SPLIT + NB_TR + NB_FOLD + NB_BIAS)

__global__ __launch_bounds__(256)
void prep_all(const float* __restrict__ X,   const float* __restrict__ Wat,
              const float* __restrict__ bat, const float* __restrict__ Sp,
              const float* __restrict__ Wp,
              float* __restrict__ xr,  float* __restrict__ wpt,
              float* __restrict__ wf,  float* __restrict__ bf)
{
    __shared__ float sbuf[128*65 + 32*64];
    const int bid = blockIdx.x;
    const int tid = threadIdx.x;

    if (bid < NB_SPLIT) {
        int i = bid * 256 + tid;
        xr[i] = rtf32(X[i]);

    } else if (bid < NB_SPLIT + NB_TR) {
        float (*sm)[33] = (float(*)[33])sbuf;
        const int rem = bid - NB_SPLIT;
        const int z  = rem >> 10;
        const int bx = (rem & 31) * 32;
        const int by = ((rem >> 5) & 31) * 32;
        const float* src; float* dst; int lds, off;
        if (z == 0) { src = Wp;  dst = wpt;           lds = 1024; off = 0;    }
        else        { src = Wat; dst = wf + 1024*D_;  lds = 3072; off = 2048; }
        const int tx = tid & 31, ty = tid >> 5;
        #pragma unroll
        for (int j = 0; j < 4; j++) {
            int r = ty*4 + j;
            sm[r][tx] = src[(long)(by + r)*lds + off + bx + tx];
        }
        __syncthreads();
        #pragma unroll
        for (int j = 0; j < 4; j++) {
            int r = ty*4 + j;
            dst[(long)(bx + r)*D_ + by + tx] = rtf32(sm[tx][r]);
        }

    } else if (bid < NB_SPLIT + NB_TR + NB_FOLD) {
        float (*slab)[65] = (float(*)[65])sbuf;
        float (*sp)[64]   = (float(*)[64])(sbuf + 128*65);
        const int rem  = bid - NB_SPLIT - NB_TR;
        const int d0   = (rem & 7) * 128;
        const int ph   = rem >> 3;
        const int part = ph >> 4, h = ph & 15;
        const int base = part*1024 + h*64;

        #pragma unroll
        for (int it = 0; it < 32; it++) {
            int i = tid + it*256;
            slab[i >> 6][i & 63] = Wat[(long)(d0 + (i >> 6))*(3*D_) + base + (i & 63)];
        }
        #pragma unroll
        for (int it = 0; it < 8; it++) {
            int i = tid + it*256;
            sp[i >> 6][i & 63] = Sp[i];
        }
        __syncthreads();

        const int dl = tid & 127;
        const int k0 = (tid >> 7) * 16;
        for (int k = k0; k < k0 + 16; k++) {
            float a = 0.f;
            #pragma unroll
            for (int e = 0; e < 64; e++) a += slab[dl][e] * sp[k][e];
            wf[(long)(part*512 + h*32 + k)*D_ + d0 + dl] = rtf32(a);
        }

    } else {
        const int i = (bid - NB_SPLIT - NB_TR - NB_FOLD) * 256 + tid;
        if (i < NF) {
            if (i < 1024) {
                const int part = i >> 9, hk = i & 511, h = hk >> 5, k = hk & 31;
                float a = 0.f;
                #pragma unroll
                for (int e = 0; e < HD_; e++)
                    a += bat[part*1024 + h*HD_ + e] * Sp[k*HD_ + e];
                bf[i] = a;
            } else {
                bf[i] = bat[2048 + (i - 1024)];
            }
        }
    }
}

// ===========================================================================
// TF32 GEMM (TN) — unchanged from round 14 (proven: 55.6us, tensor=51%).
// ===========================================================================
#define GBM 128
#define GBN 128
#define GBK 16
#define LDT 20
#define STG 3
#define TSTAGE (128*LDT*4)

__global__ __launch_bounds__(128, 2)
void tf32_gemm_tn(const float* __restrict__ A, const float* __restrict__ BT,
                  const float* __restrict__ bias, float* __restrict__ C,
                  int M, int N, int K, int roundC)
{
    extern __shared__ float dyn[];
    float* As = dyn;
    float* Bs = dyn + STG*128*LDT;

    const int tid  = threadIdx.x;
    const int wid  = tid >> 5;
    const int lane = tid & 31;
    const int g    = lane >> 2;
    const int t    = lane & 3;
    const int brow = blockIdx.y * GBM;
    const int bcol = blockIdx.x * GBN;
    const int wm   = (wid & 1) * 64;
    const int wn   = (wid >> 1) * 64;

    float4 acc[4][8];
    #pragma unroll
    for (int nt = 0; nt < 8; nt++) {
        float2 bb = *(const float2*)&bias[bcol + wn + nt*8 + 2*t];
        #pragma unroll
        for (int i = 0; i < 4; i++)
            acc[i][nt] = make_float4(bb.x, bb.y, bb.x, bb.y);
    }

    const int lr = tid >> 2;
    const int lc = (tid & 3) << 2;
    const float* Ag = A  + (long)(brow + lr)*K + lc;
    const float* Bg = BT + (long)(bcol + lr)*K + lc;
    const uint32_t sA = (uint32_t)__cvta_generic_to_shared(As);
    const uint32_t sB = (uint32_t)__cvta_generic_to_shared(Bs);
    const uint32_t ldoff = (lr*LDT + lc) * 4;

    const uint32_t a_off = (((wm + (lane & 15))*LDT) + ((lane >> 4) << 2)) * 4;
    const uint32_t b_off = (((wn + (lane & 7 ))*LDT) + ((lane >> 3) << 2)) * 4;

    const int KC = K / GBK;
    int fetch = 0;

    #pragma unroll
    for (int p = 0; p < STG - 1; p++) {
        #pragma unroll
        for (int i = 0; i < 4; i++) {
            cpa16(sA + p*TSTAGE + ldoff + i*(32*LDT*4), Ag + (long)i*32*K + fetch*GBK);
            cpa16(sB + p*TSTAGE + ldoff + i*(32*LDT*4), Bg + (long)i*32*K + fetch*GBK);
        }
        cp_commit();
        fetch++;
    }

    int s = 0;
    for (int c = 0; c < KC; c++) {
        cp_wait<STG - 2>();
        __syncthreads();

        const uint32_t aS = sA + s*TSTAGE;
        const uint32_t bS = sB + s*TSTAGE;

        uint32_t bfr[8][4];
        #pragma unroll
        for (int nt = 0; nt < 8; nt++)
            ldsm4(bfr[nt][0], bfr[nt][1], bfr[nt][2], bfr[nt][3],
                  bS + b_off + nt*(8*LDT*4));

        #pragma unroll
        for (int kk2 = 0; kk2 < 2; kk2++) {
            uint32_t af[4][4];
            #pragma unroll
            for (int i = 0; i < 4; i++)
                ldsm4(af[i][0], af[i][1], af[i][2], af[i][3],
                      aS + a_off + (i*16*LDT + kk2*8)*4);
            #pragma unroll
            for (int i = 0; i < 4; i++)
                #pragma unroll
                for (int nt = 0; nt < 8; nt++)
                    mma8(acc[i][nt], af[i], bfr[nt][kk2*2], bfr[nt][kk2*2 + 1]);
        }

        if (fetch < KC) {
            const int p = (s + STG - 1) >= STG ? s - 1 : s + STG - 1;
            #pragma unroll
            for (int i = 0; i < 4; i++) {
                cpa16(sA + p*TSTAGE + ldoff + i*(32*LDT*4), Ag + (long)i*32*K + fetch*GBK);
                cpa16(sB + p*TSTAGE + ldoff + i*(32*LDT*4), Bg + (long)i*32*K + fetch*GBK);
            }
            fetch++;
        }
        cp_commit();
        s = (s + 1 == STG) ? 0 : s + 1;
    }

    #pragma unroll
    for (int i = 0; i < 4; i++) {
        const long r0 = brow + wm + i*16 + g;
        #pragma unroll
        for (int nt = 0; nt < 8; nt++) {
            const int c0 = bcol + wn + nt*8 + 2*t;
            float4 v = acc[i][nt];
            if (roundC) {
                v.x = rtf32(v.x); v.y = rtf32(v.y);
                v.z = rtf32(v.z); v.w = rtf32(v.w);
            }
            *(float2*)&C[r0*N + c0]       = make_float2(v.x, v.y);
            *(float2*)&C[(r0 + 8)*N + c0] = make_float2(v.z, v.w);
        }
    }
}

// ===========================================================================
// Tensor-core causal flash attention (m16n8k8 tf32).
// Round-14 structure (64 q/block, 4 warps, 4 blocks/SM) with ONE change:
// S-phase K fragments via ldmatrix (64 scalar LDS -> 16 LDSM per tile;
// same mapping as the proven GEMM B path, bit-identical results).
// grid = (S/64, H, B), heavy q-tiles first.
// ===========================================================================
#define LDK 36
#define LDV 68
#define KBYTES (64*LDK*4)
#define VBYTES (64*LDV*4)

__global__ __launch_bounds__(128, 4)
void attn_mma(const float* __restrict__ x2, float* __restrict__ ao)
{
    extern __shared__ float smem[];
    float* Ks = smem;                 // [2][64*LDK]
    float* Vs = smem + 2*64*LDK;      // [2][64*LDV]

    const int tid  = threadIdx.x;
    const int w    = tid >> 5;
    const int lane = tid & 31;
    const int g    = lane >> 2;
    const int t    = lane & 3;
    const int h    = blockIdx.y;
    const int b    = blockIdx.z;
    const int qt   = gridDim.x - 1 - blockIdx.x;
    const int q0   = qt * 64;

    const uint32_t sK = (uint32_t)__cvta_generic_to_shared(Ks);
    const uint32_t sV = (uint32_t)__cvta_generic_to_shared(Vs);

    const int kr = tid >> 3, kc = (tid & 7) << 2;
    const int vr = tid >> 4, vc = (tid & 15) << 2;
    const float* kbase = x2 + (long)(b*S_) * NF + 512  + h*KJL;
    const float* vbase = x2 + (long)(b*S_) * NF + 1024 + h*HD_;

    #define LOAD_TILE(kt_, bb_)                                                 \
    {                                                                           \
        const float* kb = kbase + (long)((kt_)*64 + kr) * NF + kc;              \
        const float* vb = vbase + (long)((kt_)*64 + vr) * NF + vc;              \
        uint32_t dk = sK + (bb_)*KBYTES + (kr*LDK + kc)*4;                      \
        uint32_t dv = sV + (bb_)*VBYTES + (vr*LDV + vc)*4;                      \
        _Pragma("unroll")                                                       \
        for (int i_ = 0; i_ < 4; i_++)                                          \
            cpa16(dk + i_*(16*LDK*4), kb + (long)i_*16*NF);                     \
        _Pragma("unroll")                                                       \
        for (int i_ = 0; i_ < 8; i_++)                                          \
            cpa16(dv + i_*(8*LDV*4),  vb + (long)i_*8*NF);                      \
    }

    uint32_t qf[4][4];
    {
        const float* qb = x2 + (long)(b*S_ + q0) * NF + h*KJL;
        #pragma unroll
        for (int ks = 0; ks < 4; ks++) {
            qf[ks][0] = __float_as_uint(qb[(long)(w*16 + g    )*NF + ks*8 + t    ]);
            qf[ks][1] = __float_as_uint(qb[(long)(w*16 + g + 8)*NF + ks*8 + t    ]);
            qf[ks][2] = __float_as_uint(qb[(long)(w*16 + g    )*NF + ks*8 + t + 4]);
            qf[ks][3] = __float_as_uint(qb[(long)(w*16 + g + 8)*NF + ks*8 + t + 4]);
        }
    }

    float4 oacc[8];
    #pragma unroll
    for (int nt = 0; nt < 8; nt++) oacc[nt] = make_float4(0.f, 0.f, 0.f, 0.f);
    float m0 = -1e30f, m1 = -1e30f, l0 = 0.f, l1 = 0.f;

    const int R0 = q0 + w*16 + g;
    const int R1 = R0 + 8;
    const int nkt = qt + 1;
    const int lq0 = (lane & ~3) | (t >> 1);
    const int lq1 = lq0 + 2;
    // ldmatrix per-thread offset within K tile (same pattern as GEMM B)
    const uint32_t kf_off = (((lane & 7)*LDK) + ((lane >> 3) << 2)) * 4;

    LOAD_TILE(0, 0);
    cp_commit();

    int buf = 0;
    for (int kt = 0; kt < nkt; kt++) {
        if (kt + 1 < nkt) {
            LOAD_TILE(kt + 1, buf ^ 1);
            cp_commit();
            cp_wait<1>();
        } else {
            cp_wait<0>();
        }
        __syncthreads();

        const uint32_t sKb = sK + buf * KBYTES;
        const float* Vb = Vs + buf * (64*LDV);

        // ---- S = Q @ K^T (ldmatrix-fed B fragments) ------------------------
        float4 sa[8];
        #pragma unroll
        for (int nt = 0; nt < 8; nt++) {
            uint32_t k0[4], k1[4];
            const uint32_t a0 = sKb + kf_off + nt*(8*LDK*4);
            ldsm4(k0[0], k0[1], k0[2], k0[3], a0);        // k 0..15
            ldsm4(k1[0], k1[1], k1[2], k1[3], a0 + 64);   // k 16..31
            sa[nt] = make_float4(0.f, 0.f, 0.f, 0.f);
            mma8(sa[nt], qf[0], k0[0], k0[1]);
            mma8(sa[nt], qf[1], k0[2], k0[3]);
            mma8(sa[nt], qf[2], k1[0], k1[1]);
            mma8(sa[nt], qf[3], k1[2], k1[3]);
        }

        // ---- scale + causal mask + online softmax --------------------------
        float mx0 = -1e30f, mx1 = -1e30f;
        #pragma unroll
        for (int nt = 0; nt < 8; nt++) {
            const int c0 = kt*64 + nt*8 + 2*t;
            const int c1 = c0 + 1;
            sa[nt].x = (c0 <= R0) ? sa[nt].x * 0.125f : -1e30f;
            sa[nt].y = (c1 <= R0) ? sa[nt].y * 0.125f : -1e30f;
            sa[nt].z = (c0 <= R1) ? sa[nt].z * 0.125f : -1e30f;
            sa[nt].w = (c1 <= R1) ? sa[nt].w * 0.125f : -1e30f;
            mx0 = fmaxf(mx0, fmaxf(sa[nt].x, sa[nt].y));
            mx1 = fmaxf(mx1, fmaxf(sa[nt].z, sa[nt].w));
        }
        mx0 = fmaxf(mx0, __shfl_xor_sync(0xffffffff, mx0, 1));
        mx0 = fmaxf(mx0, __shfl_xor_sync(0xffffffff, mx0, 2));
        mx1 = fmaxf(mx1, __shfl_xor_sync(0xffffffff, mx1, 1));
        mx1 = fmaxf(mx1, __shfl_xor_sync(0xffffffff, mx1, 2));

        const float nm0 = fmaxf(m0, mx0);
        const float nm1 = fmaxf(m1, mx1);
        const float sc0 = __expf(m0 - nm0);
        const float sc1 = __expf(m1 - nm1);

        float ps0 = 0.f, ps1 = 0.f;
        #pragma unroll
        for (int nt = 0; nt < 8; nt++) {
            sa[nt].x = __expf(sa[nt].x - nm0);
            sa[nt].y = __expf(sa[nt].y - nm0);
            sa[nt].z = __expf(sa[nt].z - nm1);
            sa[nt].w = __expf(sa[nt].w - nm1);
            ps0 += sa[nt].x + sa[nt].y;
            ps1 += sa[nt].z + sa[nt].w;
        }
        ps0 += __shfl_xor_sync(0xffffffff, ps0, 1);
        ps0 += __shfl_xor_sync(0xffffffff, ps0, 2);
        ps1 += __shfl_xor_sync(0xffffffff, ps1, 1);
        ps1 += __shfl_xor_sync(0xffffffff, ps1, 2);

        l0 = l0 * sc0 + ps0;  m0 = nm0;
        l1 = l1 * sc1 + ps1;  m1 = nm1;

        #pragma unroll
        for (int nt = 0; nt < 8; nt++) {
            oacc[nt].x *= sc0;  oacc[nt].y *= sc0;
            oacc[nt].z *= sc1;  oacc[nt].w *= sc1;
        }

        // ---- O += P @ V (shuffle-based P reshape) --------------------------
        #pragma unroll
        for (int ks = 0; ks < 8; ks++) {
            float x0 = __shfl_sync(0xffffffff, sa[ks].x, lq0);
            float y0 = __shfl_sync(0xffffffff, sa[ks].y, lq0);
            float z0 = __shfl_sync(0xffffffff, sa[ks].z, lq0);
            float w0 = __shfl_sync(0xffffffff, sa[ks].w, lq0);
            float x1 = __shfl_sync(0xffffffff, sa[ks].x, lq1);
            float y1 = __shfl_sync(0xffffffff, sa[ks].y, lq1);
            float z1 = __shfl_sync(0xffffffff, sa[ks].z, lq1);
            float w1 = __shfl_sync(0xffffffff, sa[ks].w, lq1);
            uint32_t pa[4];
            pa[0] = __float_as_uint(rtf32((t & 1) ? y0 : x0));
            pa[1] = __float_as_uint(rtf32((t & 1) ? w0 : z0));
            pa[2] = __float_as_uint(rtf32((t & 1) ? y1 : x1));
            pa[3] = __float_as_uint(rtf32((t & 1) ? w1 : z1));

            const int kr0 = (ks*8 + t    ) * LDV + g;
            const int kr1 = (ks*8 + t + 4) * LDV + g;
            #pragma unroll
            for (int nt = 0; nt < 8; nt++) {
                uint32_t b0 = __float_as_uint(Vb[kr0 + nt*8]);
                uint32_t b1 = __float_as_uint(Vb[kr1 + nt*8]);
                mma8(oacc[nt], pa, b0, b1);
            }
        }
        __syncthreads();
        buf ^= 1;
    }

    const float inv0 = 1.f / l0;
    const float inv1 = 1.f / l1;
    float* o0 = ao + (long)(b*S_ + R0) * D_ + h*HD_;
    float* o1 = ao + (long)(b*S_ + R1) * D_ + h*HD_;
    #pragma unroll
    for (int nt = 0; nt < 8; nt++) {
        *(float2*)(o0 + nt*8 + 2*t) =
            make_float2(rtf32(oacc[nt].x * inv0), rtf32(oacc[nt].y * inv0));
        *(float2*)(o1 + nt*8 + 2*t) =
            make_float2(rtf32(oacc[nt].z * inv1), rtf32(oacc[nt].w * inv1));
    }
}

// ===========================================================================
extern "C" void kernel_launch(void* const* d_in, const int* in_sizes, int n_in,
                              void* d_out, int out_size)
{
    const float* X    = (const float*)d_in[0];
    const float* Wat  = (const float*)d_in[1];
    const float* bat  = (const float*)d_in[2];
    const float* Sp   = (const float*)d_in[3];
    const float* Wp   = (const float*)d_in[4];
    const float* bp   = (const float*)d_in[5];
    float* out = (float*)d_out;

    float *wf, *bf, *x2, *ao, *xr, *wpt;
    cudaGetSymbolAddress((void**)&wf,  g_wf);
    cudaGetSymbolAddress((void**)&bf,  g_bf);
    cudaGetSymbolAddress((void**)&x2,  g_x2);
    cudaGetSymbolAddress((void**)&ao,  g_ao);
    cudaGetSymbolAddress((void**)&xr,  g_xr);
    cudaGetSymbolAddress((void**)&wpt, g_wpt);

    const int gemmSmem = 2 * STG * 128 * LDT * 4;             // 61440 B
    const int attnSmem = 2 * (64*LDK + 64*LDV) * 4;           // 53248 B
    cudaFuncSetAttribute(tf32_gemm_tn,
                         cudaFuncAttributeMaxDynamicSharedMemorySize, gemmSmem);
    cudaFuncSetAttribute(attn_mma,
                         cudaFuncAttributeMaxDynamicSharedMemorySize, attnSmem);

    // 0. ALL prep in one launch
    prep_all<<<NB_ALL, 256>>>(X, Wat, bat, Sp, Wp, xr, wpt, wf, bf);

    // 1. folded QKV GEMM (epilogue rounds x2 to tf32)
    dim3 g1(NF/GBN, M_/GBM);
    tf32_gemm_tn<<<g1, 128, gemmSmem>>>(xr, wf, bf, x2, M_, NF, D_, 1);

    // 2. causal flash attention (64 queries/block, round-14 shape)
    dim3 g3(S_/64, H_, B_);
    attn_mma<<<g3, 128, attnSmem>>>(x2, ao);

    // 3. output projection GEMM (raw fp32 output)
    dim3 g4(D_/GBN, M_/GBM);
    tf32_gemm_tn<<<g4, 128, gemmSmem>>>(ao, wpt, bp, out, M_, D_, D_, 0);
}